// round 1
// baseline (speedup 1.0000x reference)
#include <cuda_runtime.h>
#include <math.h>

#define BB 2
#define HH 16
#define SS 2048
#define DD 64
#define TQ 16
#define TK 128
#define NTH 256
#define NEGV (-1000000000.0f)

struct Smem {
    float q[TQ][DD + 4];      // padded rows to dodge bank conflicts
    float kv[TK][DD + 4];     // K tile, reused as V tile
    float sc[TQ][SS];         // full score strip for 16 queries
    float red[4][64][16];     // PV cross-k-group reduction
    int   msk[TK];
};

__global__ __launch_bounds__(NTH, 1)
void attn_fused(const float* __restrict__ Q, const float* __restrict__ K,
                const float* __restrict__ V, const int* __restrict__ M,
                float* __restrict__ Out, float* __restrict__ W) {
    extern __shared__ char smraw[];
    Smem* sm = reinterpret_cast<Smem*>(smraw);
    const int t  = threadIdx.x;
    const int qt = blockIdx.x;          // query tile index (0..127)
    const int bh = blockIdx.y;          // b*H + h (0..31)
    const int b  = bh / HH;

    const float* qg = Q + ((size_t)bh * SS + (size_t)qt * TQ) * DD;
    const float* kg = K + (size_t)bh * SS * DD;
    const float* vg = V + (size_t)bh * SS * DD;
    const int*   mg = M + b * SS;

    // ---- load Q tile (16 x 64) ----
    {
        int r = t >> 4, c4 = t & 15;
        float4 val = ((const float4*)(qg + (size_t)r * DD))[c4];
        *(float4*)&sm->q[r][c4 * 4] = val;
    }

    // ---- QK^T: each thread owns 8 q-rows x 1 k-col per tile ----
    const int kq = t % TK;      // k column within tile
    const int qh = t / TK;      // 0 or 1 -> q half

    for (int kt = 0; kt < SS; kt += TK) {
        __syncthreads();
        {
            int r = t >> 4, c4 = t & 15;
            #pragma unroll
            for (int i = 0; i < TK / 16; i++) {
                float4 val = ((const float4*)(kg + (size_t)(kt + r + i * 16) * DD))[c4];
                *(float4*)&sm->kv[r + i * 16][c4 * 4] = val;
            }
            if (t < TK) sm->msk[t] = mg[kt + t];
        }
        __syncthreads();

        float acc[8];
        #pragma unroll
        for (int j = 0; j < 8; j++) acc[j] = 0.f;

        #pragma unroll
        for (int d4 = 0; d4 < DD / 4; d4++) {
            float4 kv = *(const float4*)&sm->kv[kq][d4 * 4];
            #pragma unroll
            for (int j = 0; j < 8; j++) {
                float4 qv = *(const float4*)&sm->q[qh * 8 + j][d4 * 4];
                acc[j] = fmaf(qv.x, kv.x, acc[j]);
                acc[j] = fmaf(qv.y, kv.y, acc[j]);
                acc[j] = fmaf(qv.z, kv.z, acc[j]);
                acc[j] = fmaf(qv.w, kv.w, acc[j]);
            }
        }
        const bool mz = (sm->msk[kq] == 0);
        #pragma unroll
        for (int j = 0; j < 8; j++)
            sm->sc[qh * 8 + j][kt + kq] = mz ? NEGV : acc[j] * 0.125f;
    }
    __syncthreads();

    // ---- softmax: 8 warps x 2 rows each ----
    const int w = t >> 5, l = t & 31;
    #pragma unroll
    for (int rr = 0; rr < 2; rr++) {
        const int qi = w * 2 + rr;
        float4* row4 = (float4*)&sm->sc[qi][0];

        float mx = -INFINITY;
        for (int i = l; i < SS / 4; i += 32) {
            float4 v4 = row4[i];
            mx = fmaxf(mx, fmaxf(fmaxf(v4.x, v4.y), fmaxf(v4.z, v4.w)));
        }
        #pragma unroll
        for (int off = 16; off > 0; off >>= 1)
            mx = fmaxf(mx, __shfl_xor_sync(0xffffffffu, mx, off));

        float sum = 0.f;
        for (int i = l; i < SS / 4; i += 32) {
            float4 v4 = row4[i];
            v4.x = __expf(v4.x - mx); v4.y = __expf(v4.y - mx);
            v4.z = __expf(v4.z - mx); v4.w = __expf(v4.w - mx);
            row4[i] = v4;
            sum += (v4.x + v4.y) + (v4.z + v4.w);
        }
        #pragma unroll
        for (int off = 16; off > 0; off >>= 1)
            sum += __shfl_xor_sync(0xffffffffu, sum, off);

        const float inv = 1.f / sum;
        float4* wrow4 = (float4*)(W + ((size_t)(bh * SS + qt * TQ + qi)) * SS);
        for (int i = l; i < SS / 4; i += 32) {
            float4 v4 = row4[i];
            v4.x *= inv; v4.y *= inv; v4.z *= inv; v4.w *= inv;
            row4[i]  = v4;   // keep normalized p in smem for PV
            wrow4[i] = v4;   // stream attn_weights to gmem
        }
    }
    __syncthreads();

    // ---- PV: out[q][d] = sum_k p[q][k] * v[k][d] ----
    // thread tile: 4 q-rows x 4 d (float4); k split 4 ways across thread groups
    const int kgr = t >> 6;     // 0..3 : k-stride group
    const int pos = t & 63;
    const int q4  = pos >> 4;   // 0..3 -> q rows q4*4 .. q4*4+3
    const int d4  = pos & 15;   // float4 column

    float4 acc4[4];
    #pragma unroll
    for (int j = 0; j < 4; j++) acc4[j] = make_float4(0.f, 0.f, 0.f, 0.f);

    for (int vt = 0; vt < SS; vt += TK) {
        __syncthreads();
        {
            int r = t >> 4, c4 = t & 15;
            #pragma unroll
            for (int i = 0; i < TK / 16; i++) {
                float4 val = ((const float4*)(vg + (size_t)(vt + r + i * 16) * DD))[c4];
                *(float4*)&sm->kv[r + i * 16][c4 * 4] = val;
            }
        }
        __syncthreads();

        for (int kk = kgr; kk < TK; kk += 4) {
            float4 vv = *(const float4*)&sm->kv[kk][d4 * 4];
            #pragma unroll
            for (int j = 0; j < 4; j++) {
                float p = sm->sc[q4 * 4 + j][vt + kk];
                acc4[j].x = fmaf(p, vv.x, acc4[j].x);
                acc4[j].y = fmaf(p, vv.y, acc4[j].y);
                acc4[j].z = fmaf(p, vv.z, acc4[j].z);
                acc4[j].w = fmaf(p, vv.w, acc4[j].w);
            }
        }
    }

    // reduce across the 4 k-groups
    #pragma unroll
    for (int j = 0; j < 4; j++)
        *(float4*)&sm->red[kgr][pos][j * 4] = acc4[j];
    __syncthreads();

    #pragma unroll
    for (int oi = 0; oi < 4; oi++) {
        int o  = t + oi * 256;     // 0..1023
        int qq = o >> 6;           // 0..15
        int dd = o & 63;
        int p  = (qq >> 2) * 16 + (dd >> 2);
        int s  = (qq & 3) * 4 + (dd & 3);
        float val = sm->red[0][p][s] + sm->red[1][p][s]
                  + sm->red[2][p][s] + sm->red[3][p][s];
        Out[((size_t)(bh * SS + qt * TQ + qq)) * DD + dd] = val;
    }
}

extern "C" void kernel_launch(void* const* d_in, const int* in_sizes, int n_in,
                              void* d_out, int out_size) {
    const float* q = (const float*)d_in[0];
    const float* k = (const float*)d_in[1];
    const float* v = (const float*)d_in[2];
    const int*   m = (const int*)d_in[3];

    float* out = (float*)d_out;
    float* wts = out + (size_t)BB * HH * SS * DD;   // output first, attn_weights second

    size_t smem = sizeof(Smem);
    cudaFuncSetAttribute(attn_fused, cudaFuncAttributeMaxDynamicSharedMemorySize, (int)smem);

    dim3 grid(SS / TQ, BB * HH);
    attn_fused<<<grid, NTH, smem>>>(q, k, v, m, out, wts);
}

// round 3
// speedup vs baseline: 2.6565x; 2.6565x over previous
#include <cuda_runtime.h>
#include <cuda_bf16.h>
#include <cstdint>
#include <math.h>

#define BB 2
#define HH 16
#define SQ 2048
#define DDIM 64
#define MQ 128
#define TKEY 128
#define NTILE (SQ / TKEY)
#define NTH 256
#define NEGV (-1000000000.0f)

// smem (u32 units): KH[2][4096] KL[2][4096] VH[2][4096] VL[2][4096] BIAS[2][128] LSUM[128] INV[128]
#define SM_U32 (8 * 4096 + 2 * 128 + 128 + 128)
#define SMEM_BYTES (SM_U32 * 4)

static __device__ __forceinline__ void mma_bf16(float* c, const uint32_t* a, const uint32_t* b) {
    asm volatile(
        "mma.sync.aligned.m16n8k16.row.col.f32.bf16.bf16.f32 "
        "{%0,%1,%2,%3}, {%4,%5,%6,%7}, {%8,%9}, {%0,%1,%2,%3};"
        : "+f"(c[0]), "+f"(c[1]), "+f"(c[2]), "+f"(c[3])
        : "r"(a[0]), "r"(a[1]), "r"(a[2]), "r"(a[3]), "r"(b[0]), "r"(b[1]));
}

static __device__ __forceinline__ void split2(float a, float b, uint32_t& hi, uint32_t& lo) {
    __nv_bfloat162 h = __floats2bfloat162_rn(a, b);
    float ra = a - __bfloat162float(__low2bfloat16(h));
    float rb = b - __bfloat162float(__high2bfloat16(h));
    __nv_bfloat162 l = __floats2bfloat162_rn(ra, rb);
    hi = *reinterpret_cast<uint32_t*>(&h);
    lo = *reinterpret_cast<uint32_t*>(&l);
}

__global__ __launch_bounds__(NTH, 1)
void attn_mma(const float* __restrict__ Q, const float* __restrict__ K,
              const float* __restrict__ V, const int* __restrict__ M,
              float* __restrict__ Out, float* __restrict__ W) {
    extern __shared__ __align__(16) uint32_t smu[];
    uint32_t* KH[2] = { smu,          smu + 4096  };
    uint32_t* KL[2] = { smu + 8192,   smu + 12288 };
    uint32_t* VH[2] = { smu + 16384,  smu + 20480 };
    uint32_t* VL[2] = { smu + 24576,  smu + 28672 };
    float*    BIAS  = (float*)(smu + 32768);   // [2][128]
    float*    LSUM  = (float*)(smu + 33024);
    float*    INVL  = (float*)(smu + 33152);

    const int t    = threadIdx.x;
    const int wid  = t >> 5;
    const int lane = t & 31;
    const int g    = lane >> 2;       // group id (row within frag)
    const int t4   = lane & 3;
    const int qb   = wid * 16;        // this warp's q-row base within tile

    const int qt = blockIdx.x;        // 0..15
    const int bh = blockIdx.y;        // 0..31
    const int b  = bh / HH;

    const float* qg = Q + ((size_t)bh * SQ + (size_t)qt * MQ) * DDIM;
    const float* kg = K + (size_t)bh * SQ * DDIM;
    const float* vg = V + (size_t)bh * SQ * DDIM;
    const int*   mg = M + b * SQ;

    // ---- persistent Q A-fragments (hi/lo) ----
    uint32_t AH[4][4], AL[4][4];
    #pragma unroll
    for (int kc = 0; kc < 4; kc++) {
        const float* r0 = qg + (size_t)(qb + g) * DDIM + kc * 16 + 2 * t4;
        const float* r1 = r0 + 8 * DDIM;
        float2 p0 = *(const float2*)(r0);
        float2 p1 = *(const float2*)(r1);
        float2 p2 = *(const float2*)(r0 + 8);
        float2 p3 = *(const float2*)(r1 + 8);
        split2(p0.x, p0.y, AH[kc][0], AL[kc][0]);
        split2(p1.x, p1.y, AH[kc][1], AL[kc][1]);
        split2(p2.x, p2.y, AH[kc][2], AL[kc][2]);
        split2(p3.x, p3.y, AH[kc][3], AL[kc][3]);
    }

    // ---- loaders ----
    // K tile: frag slot(nt,kcd,lane,r) = nt*256 + kcd*64 + lane*2 + r
    auto ldgK = [&](int kt, float2* xk) {
        const float2* kp2 = (const float2*)(kg + (size_t)kt * TKEY * DDIM);
        #pragma unroll
        for (int i = 0; i < 16; i++) xk[i] = kp2[i * NTH + t];
    };
    auto stsK = [&](int buf, const float2* xk) {
        #pragma unroll
        for (int i = 0; i < 16; i++) {
            int idx = i * NTH + t;
            int key = idx >> 5, dp = idx & 31;
            int nt = key >> 3, gg = key & 7;
            int kcd = dp >> 3, tt = dp & 3, r = (dp >> 2) & 1;
            int slot = nt * 256 + kcd * 64 + (gg * 4 + tt) * 2 + r;
            uint32_t hi, lo; split2(xk[i].x, xk[i].y, hi, lo);
            KH[buf][slot] = hi; KL[buf][slot] = lo;
        }
    };
    // V tile: frag slot(kc2,ntd,lane,r) = kc2*512 + ntd*64 + lane*2 + r
    auto ldgV = [&](int kt, float* va, float* vb) {
        #pragma unroll
        for (int i = 0; i < 16; i++) {
            int idx = i * NTH + t;
            int d = idx & 63, kp = idx >> 6;
            const float* base = vg + ((size_t)kt * TKEY + 2 * kp) * DDIM + d;
            va[i] = base[0];
            vb[i] = base[DDIM];
        }
    };
    auto stsV = [&](int buf, const float* va, const float* vb) {
        #pragma unroll
        for (int i = 0; i < 16; i++) {
            int idx = i * NTH + t;
            int d = idx & 63, kp = idx >> 6;
            int kc2 = kp >> 3, w8 = kp & 7;
            int tt = w8 & 3, r = w8 >> 2;
            int ntd = d >> 3, gg = d & 7;
            int slot = kc2 * 512 + ntd * 64 + (gg * 4 + tt) * 2 + r;
            uint32_t hi, lo; split2(va[i], vb[i], hi, lo);
            VH[buf][slot] = hi; VL[buf][slot] = lo;
        }
    };
    auto ldgBias = [&](int kt) -> float {
        if (t < TKEY) { int mv = mg[kt * TKEY + t]; return mv ? 0.f : NEGV; }
        return 0.f;
    };

    // QK for one 16-key chunk -> c[2][4]
    auto qk_chunk = [&](int buf, int kc2, float c[2][4]) {
        #pragma unroll
        for (int i = 0; i < 2; i++) {
            int nt = kc2 * 2 + i;
            #pragma unroll
            for (int kcd = 0; kcd < 4; kcd++) {
                uint32_t bhh[2], bll[2];
                *(uint2*)bhh = *(const uint2*)&KH[buf][nt * 256 + kcd * 64 + lane * 2];
                *(uint2*)bll = *(const uint2*)&KL[buf][nt * 256 + kcd * 64 + lane * 2];
                mma_bf16(c[i], AH[kcd], bhh);
                mma_bf16(c[i], AH[kcd], bll);
                mma_bf16(c[i], AL[kcd], bhh);
            }
        }
    };

    // ================= preload tile 0 (K + bias) =================
    {
        float2 xk[16]; ldgK(0, xk);
        float bv = ldgBias(0);
        stsK(0, xk);
        if (t < TKEY) BIAS[t] = bv;
    }
    __syncthreads();

    // ================= PASS 1: row sums =================
    float rs0 = 0.f, rs1 = 0.f;
    for (int kt = 0; kt < NTILE; kt++) {
        const int cur = kt & 1, nxt = cur ^ 1;
        float2 xk[16]; float bv = 0.f;
        if (kt < NTILE - 1) { ldgK(kt + 1, xk); bv = ldgBias(kt + 1); }

        #pragma unroll
        for (int kc2 = 0; kc2 < 8; kc2++) {
            float c[2][4] = {{0,0,0,0},{0,0,0,0}};
            qk_chunk(cur, kc2, c);
            #pragma unroll
            for (int i = 0; i < 2; i++) {
                int colb = (kc2 * 2 + i) * 8 + 2 * t4;
                float b0 = BIAS[cur * 128 + colb], b1 = BIAS[cur * 128 + colb + 1];
                rs0 += __expf(c[i][0] * 0.125f + b0);
                rs0 += __expf(c[i][1] * 0.125f + b1);
                rs1 += __expf(c[i][2] * 0.125f + b0);
                rs1 += __expf(c[i][3] * 0.125f + b1);
            }
        }
        if (kt < NTILE - 1) {
            stsK(nxt, xk);
            if (t < TKEY) BIAS[nxt * 128 + t] = bv;
        }
        __syncthreads();
    }
    rs0 += __shfl_xor_sync(0xffffffffu, rs0, 1);
    rs0 += __shfl_xor_sync(0xffffffffu, rs0, 2);
    rs1 += __shfl_xor_sync(0xffffffffu, rs1, 1);
    rs1 += __shfl_xor_sync(0xffffffffu, rs1, 2);
    if (t4 == 0) { LSUM[qb + g] = rs0; LSUM[qb + g + 8] = rs1; }
    __syncthreads();
    if (t < MQ) INVL[t] = 1.f / LSUM[t];

    // reload tile 0 (K + V + bias) into buf 0
    {
        float2 xk[16]; ldgK(0, xk);
        float va[16], vb[16]; ldgV(0, va, vb);
        float bvv = ldgBias(0);
        stsK(0, xk); stsV(0, va, vb);
        if (t < TKEY) BIAS[t] = bvv;
    }
    __syncthreads();

    const float inv0 = INVL[qb + g];
    const float inv1 = INVL[qb + g + 8];

    float* wr0 = W + ((size_t)bh * SQ + qt * MQ + qb + g) * SQ;
    float* wr1 = wr0 + (size_t)8 * SQ;

    // ================= PASS 2: W write + PV =================
    float accO[8][4];
    #pragma unroll
    for (int j = 0; j < 8; j++)
        accO[j][0] = accO[j][1] = accO[j][2] = accO[j][3] = 0.f;

    for (int kt = 0; kt < NTILE; kt++) {
        const int cur = kt & 1, nxt = cur ^ 1;
        float2 xk[16]; float va[16], vb[16]; float bv = 0.f;
        if (kt < NTILE - 1) { ldgK(kt + 1, xk); ldgV(kt + 1, va, vb); bv = ldgBias(kt + 1); }

        #pragma unroll
        for (int kc2 = 0; kc2 < 8; kc2++) {
            float c[2][4] = {{0,0,0,0},{0,0,0,0}};
            qk_chunk(cur, kc2, c);

            float e[2][4];
            #pragma unroll
            for (int i = 0; i < 2; i++) {
                int colb = (kc2 * 2 + i) * 8 + 2 * t4;
                float b0 = BIAS[cur * 128 + colb], b1 = BIAS[cur * 128 + colb + 1];
                e[i][0] = __expf(c[i][0] * 0.125f + b0) * inv0;
                e[i][1] = __expf(c[i][1] * 0.125f + b1) * inv0;
                e[i][2] = __expf(c[i][2] * 0.125f + b0) * inv1;
                e[i][3] = __expf(c[i][3] * 0.125f + b1) * inv1;
            }
            // W stores (float2, quad-contiguous 32B)
            {
                size_t cb = (size_t)kt * TKEY + kc2 * 16 + 2 * t4;
                *(float2*)(wr0 + cb)     = make_float2(e[0][0], e[0][1]);
                *(float2*)(wr1 + cb)     = make_float2(e[0][2], e[0][3]);
                *(float2*)(wr0 + cb + 8) = make_float2(e[1][0], e[1][1]);
                *(float2*)(wr1 + cb + 8) = make_float2(e[1][2], e[1][3]);
            }
            // repack to PV A-frags
            uint32_t aWH[4], aWL[4];
            split2(e[0][0], e[0][1], aWH[0], aWL[0]);
            split2(e[0][2], e[0][3], aWH[1], aWL[1]);
            split2(e[1][0], e[1][1], aWH[2], aWL[2]);
            split2(e[1][2], e[1][3], aWH[3], aWL[3]);
            // PV over 8 d-tiles
            #pragma unroll
            for (int ntd = 0; ntd < 8; ntd++) {
                uint32_t bhh[2], bll[2];
                *(uint2*)bhh = *(const uint2*)&VH[cur][kc2 * 512 + ntd * 64 + lane * 2];
                *(uint2*)bll = *(const uint2*)&VL[cur][kc2 * 512 + ntd * 64 + lane * 2];
                mma_bf16(accO[ntd], aWH, bhh);
                mma_bf16(accO[ntd], aWH, bll);
                mma_bf16(accO[ntd], aWL, bhh);
            }
        }
        if (kt < NTILE - 1) {
            stsK(nxt, xk); stsV(nxt, va, vb);
            if (t < TKEY) BIAS[nxt * 128 + t] = bv;
        }
        __syncthreads();
    }

    // ---- output ----
    float* or0 = Out + ((size_t)bh * SQ + qt * MQ + qb + g) * DDIM + 2 * t4;
    float* or1 = or0 + (size_t)8 * DDIM;
    #pragma unroll
    for (int ntd = 0; ntd < 8; ntd++) {
        *(float2*)(or0 + ntd * 8) = make_float2(accO[ntd][0], accO[ntd][1]);
        *(float2*)(or1 + ntd * 8) = make_float2(accO[ntd][2], accO[ntd][3]);
    }
}

extern "C" void kernel_launch(void* const* d_in, const int* in_sizes, int n_in,
                              void* d_out, int out_size) {
    const float* q = (const float*)d_in[0];
    const float* k = (const float*)d_in[1];
    const float* v = (const float*)d_in[2];
    const int*   m = (const int*)d_in[3];

    float* out = (float*)d_out;
    float* wts = out + (size_t)BB * HH * SQ * DDIM;

    cudaFuncSetAttribute(attn_mma, cudaFuncAttributeMaxDynamicSharedMemorySize, SMEM_BYTES);
    dim3 grid(SQ / MQ, BB * HH);
    attn_mma<<<grid, NTH, SMEM_BYTES>>>(q, k, v, m, out, wts);
}